// round 16
// baseline (speedup 1.0000x reference)
#include <cuda_runtime.h>
#include <cuda_bf16.h>

#define T_STEPS 512
#define BATCH   64
#define DIN     256
#define DH      1024
#define DOUT    256
#define BH      (BATCH * DH)      // 65536
#define SCAN_CTAS 64              // 2 chains per CTA
#define DOM_ARRIVALS 32           // 32 CTAs per row-group domain
#define SA_STRIDE 1032            // scan: padded bf16 row stride (R11 proven)
#define AS 264                    // GEMM: padded bf16 row stride

typedef unsigned long long ull;
typedef unsigned int uint32;

// Scratch (device globals: allocation-free per harness rules)
__device__ float g_xp[T_STEPS * BH];                 // [T][B][H] input projection
__device__ __nv_bfloat16 g_hs_hi[T_STEPS * BH];      // h high bf16
__device__ __nv_bfloat16 g_hs_lo[T_STEPS * BH];      // h residual bf16
__device__ unsigned int g_barG[T_STEPS * 4 * 32];    // (step, rowgroup) counters
__device__ uint4 g_WiF[128 * 16 * 32];               // W_in  B-frags [nblk][kt][lane]
__device__ uint4 g_WoF[32 * 64 * 32];                // W_out B-frags [nblk][kt][lane]

// ---- bf16 split helpers ---------------------------------------------------
__device__ __forceinline__ void split_bf16(float v, __nv_bfloat16& hi, __nv_bfloat16& lo) {
    hi = __float2bfloat16_rn(v);
    lo = __float2bfloat16_rn(v - __bfloat162float(hi));
}
__device__ __forceinline__ uint32 pack_bf2(__nv_bfloat16 a, __nv_bfloat16 b) {
    __nv_bfloat162 p;
    p.x = a; p.y = b;
    return *(uint32*)&p;
}

// ---- mma / ldmatrix helpers (validated R10/R11) ---------------------------
__device__ __forceinline__ void mma_bf16(float& d0, float& d1, float& d2, float& d3,
                                         uint32 a0, uint32 a1, uint32 a2, uint32 a3,
                                         uint32 b0, uint32 b1) {
    asm volatile(
        "mma.sync.aligned.m16n8k16.row.col.f32.bf16.bf16.f32 "
        "{%0,%1,%2,%3}, {%4,%5,%6,%7}, {%8,%9}, {%0,%1,%2,%3};"
        : "+f"(d0), "+f"(d1), "+f"(d2), "+f"(d3)
        : "r"(a0), "r"(a1), "r"(a2), "r"(a3), "r"(b0), "r"(b1));
}
__device__ __forceinline__ void ldsm_x4(uint32& r0, uint32& r1, uint32& r2, uint32& r3,
                                        uint32 saddr) {
    asm volatile("ldmatrix.sync.aligned.m8n8.x4.shared.b16 {%0,%1,%2,%3}, [%4];"
                 : "=r"(r0), "=r"(r1), "=r"(r2), "=r"(r3) : "r"(saddr));
}

// ---------------------------------------------------------------------------
// Prep: split-bf16 B-fragment arrays for W_in and W_out (validated R11).
// ---------------------------------------------------------------------------
__device__ __forceinline__ uint4 make_frag(const float* __restrict__ W, int ldn,
                                           int n, int k) {
    float w00 = W[k * ldn + n],       w01 = W[(k + 1) * ldn + n];
    float w10 = W[(k + 8) * ldn + n], w11 = W[(k + 9) * ldn + n];
    __nv_bfloat16 h00, l00, h01, l01, h10, l10, h11, l11;
    split_bf16(w00, h00, l00); split_bf16(w01, h01, l01);
    split_bf16(w10, h10, l10); split_bf16(w11, h11, l11);
    uint4 v;
    v.x = pack_bf2(h00, h01);
    v.y = pack_bf2(h10, h11);
    v.z = pack_bf2(l00, l01);
    v.w = pack_bf2(l10, l11);
    return v;
}

__global__ void k_prep(const float* __restrict__ Wi, const float* __restrict__ Wo) {
    int idx = blockIdx.x * 256 + threadIdx.x;
    if (idx < 128 * 16 * 32) {
        int lane = idx & 31;
        int kt   = (idx >> 5) & 15;
        int nblk = idx >> 9;
        g_WiF[idx] = make_frag(Wi, DH, nblk * 8 + (lane >> 2), kt * 16 + 2 * (lane & 3));
    } else {
        int j = idx - 128 * 16 * 32;
        int lane = j & 31;
        int kt   = (j >> 5) & 63;
        int nblk = j >> 11;
        g_WoF[j] = make_frag(Wo, DOUT, nblk * 8 + (lane >> 2), kt * 16 + 2 * (lane & 3));
    }
}

// ---------------------------------------------------------------------------
// Kernel A (tensor): x_proj = x @ W_in + bias. ONE CTA per t (R14/15 body).
// ---------------------------------------------------------------------------
__global__ void __launch_bounds__(256, 1) k_xproj_mma(const float* __restrict__ x,
                                                      const float* __restrict__ bias) {
    extern __shared__ __align__(16) char smem_raw[];
    __nv_bfloat16* sAhi = (__nv_bfloat16*)smem_raw;   // [64][AS]
    __nv_bfloat16* sAlo = sAhi + 64 * AS;

    const int tid = threadIdx.x, w = tid >> 5, lane = tid & 31;
    const int t = blockIdx.x;
    const int mt = w & 3, nh = w >> 2;
    uint32 abase_hi = (uint32)__cvta_generic_to_shared(sAhi);
    uint32 abase_lo = (uint32)__cvta_generic_to_shared(sAlo);
    const uint32 lane_off = ((uint32)((mt * 16 + (lane & 15)) * AS) +
                            (uint32)((lane >> 4) * 8)) * 2u;
    const int g = lane >> 2, q = lane & 3;

#pragma unroll
    for (int i = 0; i < 16; i++) {
        int c = tid + 256 * i;
        int row = c >> 6, off = c & 63;
        float4 v = ((const float4*)(x + ((size_t)row * T_STEPS + t) * DIN))[off];
        __nv_bfloat16 h0, l0, h1, l1, h2, l2, h3, l3;
        split_bf16(v.x, h0, l0); split_bf16(v.y, h1, l1);
        split_bf16(v.z, h2, l2); split_bf16(v.w, h3, l3);
        uint2 ph, pl;
        ph.x = pack_bf2(h0, h1); ph.y = pack_bf2(h2, h3);
        pl.x = pack_bf2(l0, l1); pl.y = pack_bf2(l2, l3);
        *(uint2*)&sAhi[row * AS + off * 4] = ph;
        *(uint2*)&sAlo[row * AS + off * 4] = pl;
    }
    __syncthreads();

    for (int nb = 0; nb < 8; nb++) {
        const int n0 = nb * 128;
        float C[8][4] = {};
#pragma unroll
        for (int kt = 0; kt < 16; kt++) {
            uint32 ah0, ah1, ah2, ah3, al0, al1, al2, al3;
            ldsm_x4(ah0, ah1, ah2, ah3, abase_hi + lane_off + (uint32)(kt * 32));
            ldsm_x4(al0, al1, al2, al3, abase_lo + lane_off + (uint32)(kt * 32));
#pragma unroll
            for (int nt = 0; nt < 8; nt++) {
                int nblk = (n0 >> 3) + nh * 8 + nt;
                uint4 bf = g_WiF[(nblk * 16 + kt) * 32 + lane];
                mma_bf16(C[nt][0], C[nt][1], C[nt][2], C[nt][3],
                         ah0, ah1, ah2, ah3, bf.x, bf.y);
                mma_bf16(C[nt][0], C[nt][1], C[nt][2], C[nt][3],
                         ah0, ah1, ah2, ah3, bf.z, bf.w);
                mma_bf16(C[nt][0], C[nt][1], C[nt][2], C[nt][3],
                         al0, al1, al2, al3, bf.x, bf.y);
            }
        }
#pragma unroll
        for (int nt = 0; nt < 8; nt++) {
            int n = n0 + nh * 64 + nt * 8 + 2 * q;
            float2 bv = *(const float2*)&bias[n];
            int m0 = mt * 16 + g;
            float2 v0; v0.x = C[nt][0] + bv.x; v0.y = C[nt][1] + bv.y;
            *(float2*)&g_xp[(size_t)t * BH + m0 * DH + n] = v0;
            float2 v1; v1.x = C[nt][2] + bv.x; v1.y = C[nt][3] + bv.y;
            *(float2*)&g_xp[(size_t)t * BH + (m0 + 8) * DH + n] = v1;
        }
    }
}

// ---------------------------------------------------------------------------
// Barrier primitives: split arrive / poll (R9-proven REDG + relaxed spin)
// ---------------------------------------------------------------------------
__device__ __forceinline__ unsigned int* rg_ctr(int rb, int t) {
    return &g_barG[(t * 4 + rb) * 32];
}

__device__ __forceinline__ void dom_arrive(int rb, int t) {
    __syncthreads();   // all h stores of this CTA happen-before the release
    if (threadIdx.x == 0) {
        asm volatile("red.release.gpu.global.add.u32 [%0], 1;"
                     :: "l"(rg_ctr(rb, t)) : "memory");
    }
}

__device__ __forceinline__ void dom_poll(int rb, int t, bool resetter) {
    if (threadIdx.x == 0) {
        unsigned int* ctr = rg_ctr(rb, t);
        unsigned int v;
        do {
            asm volatile("ld.relaxed.gpu.global.u32 %0, [%1];"
                         : "=r"(v) : "l"(ctr) : "memory");
        } while (v < DOM_ARRIVALS);
        asm volatile("ld.acquire.gpu.global.u32 %0, [%1];"
                     : "=r"(v) : "l"(ctr) : "memory");
        // everyone arrived at t => everyone passed poll(t-1): t-1 counter dead
        if (resetter && t >= 1) {
            asm volatile("st.relaxed.gpu.global.u32 [%0], 0;"
                         :: "l"(rg_ctr(rb, t - 1)) : "memory");
        }
    }
    __syncthreads();   // acquire edge propagates to all threads
}

// ---------------------------------------------------------------------------
// Kernel B: persistent tensor-core scan, TWO interleaved row-group chains
// per CTA. 64 CTAs: p = bid>>5 in {0,1}, cb = bid&31. Chain A = rowgroup p,
// chain B = rowgroup p+2 (rows rb*16..+16), both on cols [32cb,32cb+32) —
// W registers shared between chains. Each chain's barrier round-trip hides
// behind the other chain's compute. Phase body = exact R11 step.
// ---------------------------------------------------------------------------
#define SCAN_PHASE(rb_, t_)                                                    \
    do {                                                                       \
        const int row0_ = (rb_) * 16;                                          \
        const int grow_ = row0_ + erow;                                        \
        float2 xv = *(const float2*)&g_xp[(size_t)(t_) * BH + grow_ * DH + gcol]; \
        dom_poll(rb_, (t_) - 1, resetter);                                     \
        {                                                                      \
            const uint4* srcH = (const uint4*)(g_hs_hi + (size_t)((t_) - 1) * BH + row0_ * DH); \
            const uint4* srcL = (const uint4*)(g_hs_lo + (size_t)((t_) - 1) * BH + row0_ * DH); \
            _Pragma("unroll")                                                  \
            for (int i = 0; i < 8; i++) {                                      \
                int c   = tid + 256 * i;                                       \
                int row = c >> 7;                                              \
                int off = c & 127;                                             \
                *(uint4*)(sA_hi + row * SA_STRIDE + off * 8) = srcH[c];        \
                *(uint4*)(sA_lo + row * SA_STRIDE + off * 8) = srcL[c];        \
            }                                                                  \
        }                                                                      \
        __syncthreads();                                                       \
        float C[4][4];                                                         \
        _Pragma("unroll")                                                      \
        for (int nt = 0; nt < 4; nt++)                                         \
            _Pragma("unroll")                                                  \
            for (int i = 0; i < 4; i++) C[nt][i] = 0.f;                        \
        _Pragma("unroll")                                                      \
        for (int kt = 0; kt < 8; kt++) {                                       \
            uint32 ah0, ah1, ah2, ah3, al0, al1, al2, al3;                     \
            ldsm_x4(ah0, ah1, ah2, ah3, sa_hi_base + lane_off + (uint32)(kt * 32)); \
            ldsm_x4(al0, al1, al2, al3, sa_lo_base + lane_off + (uint32)(kt * 32)); \
            _Pragma("unroll")                                                  \
            for (int nt = 0; nt < 4; nt++) {                                   \
                mma_bf16(C[nt][0], C[nt][1], C[nt][2], C[nt][3],               \
                         ah0, ah1, ah2, ah3, Bhi[nt][kt][0], Bhi[nt][kt][1]);  \
                mma_bf16(C[nt][0], C[nt][1], C[nt][2], C[nt][3],               \
                         ah0, ah1, ah2, ah3, Blo[nt][kt][0], Blo[nt][kt][1]);  \
                mma_bf16(C[nt][0], C[nt][1], C[nt][2], C[nt][3],               \
                         al0, al1, al2, al3, Bhi[nt][kt][0], Bhi[nt][kt][1]);  \
            }                                                                  \
        }                                                                      \
        {                                                                      \
            const int g_ = lane >> 2;                                          \
            const int q_ = lane & 3;                                           \
            float* base = sRed + w * 512;                                      \
            _Pragma("unroll")                                                  \
            for (int nt = 0; nt < 4; nt++) {                                   \
                const int coln = nt * 8 + 2 * q_;                              \
                float2 lo2; lo2.x = C[nt][0]; lo2.y = C[nt][1];                \
                float2 hi2; hi2.x = C[nt][2]; hi2.y = C[nt][3];                \
                *(float2*)&base[g_ * 32 + coln]       = lo2;                   \
                *(float2*)&base[(g_ + 8) * 32 + coln] = hi2;                   \
            }                                                                  \
        }                                                                      \
        __syncthreads();                                                       \
        {                                                                      \
            const int o = erow * 32 + ecol;                                    \
            float2 s = {0.f, 0.f};                                             \
            _Pragma("unroll")                                                  \
            for (int ww = 0; ww < 8; ww++) {                                   \
                float2 v = *(const float2*)&sRed[ww * 512 + o];                \
                s.x += v.x;                                                    \
                s.y += v.y;                                                    \
            }                                                                  \
            float v0 = tanhf(xv.x + s.x);                                      \
            float v1 = tanhf(xv.y + s.y);                                      \
            __nv_bfloat16 h0, l0, h1, l1;                                      \
            split_bf16(v0, h0, l0);                                            \
            split_bf16(v1, h1, l1);                                            \
            *(uint32*)&g_hs_hi[(size_t)(t_) * BH + grow_ * DH + gcol] = pack_bf2(h0, h1); \
            *(uint32*)&g_hs_lo[(size_t)(t_) * BH + grow_ * DH + gcol] = pack_bf2(l0, l1); \
        }                                                                      \
        if ((t_) != T_STEPS - 1) dom_arrive(rb_, t_);                          \
    } while (0)

__global__ void __launch_bounds__(256, 1) k_scan(const float* __restrict__ Wh) {
    extern __shared__ __align__(16) char smem_raw[];
    __nv_bfloat16* sA_hi = (__nv_bfloat16*)smem_raw;                  // [16][SA_STRIDE]
    __nv_bfloat16* sA_lo = sA_hi + 16 * SA_STRIDE;                    // [16][SA_STRIDE]
    float*         sRed  = (float*)(sA_lo + 16 * SA_STRIDE);          // [8][512]

    const int tid  = threadIdx.x;
    const int w    = tid >> 5;
    const int lane = tid & 31;
    const int p    = blockIdx.x >> 5;          // 0..1
    const int cb   = blockIdx.x & 31;          // 0..31
    const int rbA  = p;                        // chain A row group
    const int rbB  = p + 2;                    // chain B row group
    const bool resetter = (cb == 0);

    // entry reset: only counters t = T_STEPS-2 survive the previous launch
    if (resetter && tid == 0) {
        *rg_ctr(rbA, T_STEPS - 2) = 0;
        *rg_ctr(rbB, T_STEPS - 2) = 0;
    }

    // W fragments (depend on cb only — shared by both chains)
    uint32 Bhi[4][8][2], Blo[4][8][2];
    {
        const int nn = cb * 32 + (lane >> 2);
#pragma unroll
        for (int nt = 0; nt < 4; nt++) {
            const int n = nn + nt * 8;
#pragma unroll
            for (int kt = 0; kt < 8; kt++) {
                const int kbase = w * 128 + kt * 16 + 2 * (lane & 3);
#pragma unroll
                for (int half = 0; half < 2; half++) {
                    const int k = kbase + half * 8;
                    float w0 = Wh[k * DH + n];
                    float w1 = Wh[(k + 1) * DH + n];
                    __nv_bfloat16 h0, l0, h1, l1;
                    split_bf16(w0, h0, l0);
                    split_bf16(w1, h1, l1);
                    Bhi[nt][kt][half] = pack_bf2(h0, h1);
                    Blo[nt][kt][half] = pack_bf2(l0, l1);
                }
            }
        }
    }

    const int erow = tid >> 4;
    const int ecol = (tid & 15) * 2;
    const int gcol = cb * 32 + ecol;

    uint32 sa_hi_base = (uint32)__cvta_generic_to_shared(sA_hi);
    uint32 sa_lo_base = (uint32)__cvta_generic_to_shared(sA_lo);
    const uint32 lane_off = ((uint32)(lane & 15) * SA_STRIDE + (uint32)(w * 128) +
                            (uint32)((lane >> 4) * 8)) * 2u;

    // t = 0: h = tanh(xp) for both chains
    {
        const int growA = rbA * 16 + erow;
        float2 xv = *(const float2*)&g_xp[growA * DH + gcol];
        float v0 = tanhf(xv.x), v1 = tanhf(xv.y);
        __nv_bfloat16 h0, l0, h1, l1;
        split_bf16(v0, h0, l0);
        split_bf16(v1, h1, l1);
        *(uint32*)&g_hs_hi[growA * DH + gcol] = pack_bf2(h0, h1);
        *(uint32*)&g_hs_lo[growA * DH + gcol] = pack_bf2(l0, l1);
    }
    dom_arrive(rbA, 0);
    {
        const int growB = rbB * 16 + erow;
        float2 xv = *(const float2*)&g_xp[growB * DH + gcol];
        float v0 = tanhf(xv.x), v1 = tanhf(xv.y);
        __nv_bfloat16 h0, l0, h1, l1;
        split_bf16(v0, h0, l0);
        split_bf16(v1, h1, l1);
        *(uint32*)&g_hs_hi[growB * DH + gcol] = pack_bf2(h0, h1);
        *(uint32*)&g_hs_lo[growB * DH + gcol] = pack_bf2(l0, l1);
    }
    dom_arrive(rbB, 0);

    for (int t = 1; t < T_STEPS; t++) {
        SCAN_PHASE(rbA, t);
        SCAN_PHASE(rbB, t);
    }
}

// ---------------------------------------------------------------------------
// Kernel C (tensor): out = hs @ W_out + bias. ONE CTA per t (R14 body).
// ---------------------------------------------------------------------------
__global__ void __launch_bounds__(256, 1) k_out_mma(const float* __restrict__ bias,
                                                    float* __restrict__ out) {
    extern __shared__ __align__(16) char smem_raw[];
    __nv_bfloat16* sAhi = (__nv_bfloat16*)smem_raw;   // [64][AS]
    __nv_bfloat16* sAlo = sAhi + 64 * AS;

    const int tid = threadIdx.x, w = tid >> 5, lane = tid & 31;
    const int t = blockIdx.x;
    const int mt = w & 3, nh = w >> 2;
    uint32 abase_hi = (uint32)__cvta_generic_to_shared(sAhi);
    uint32 abase_lo = (uint32)__cvta_generic_to_shared(sAlo);
    const uint32 lane_off = ((uint32)((mt * 16 + (lane & 15)) * AS) +
                            (uint32)((lane >> 4) * 8)) * 2u;
    const int g = lane >> 2, q = lane & 3;

    float C[2][8][4] = {};

    for (int kc = 0; kc < 4; kc++) {
#pragma unroll
        for (int i = 0; i < 8; i++) {
            int c = tid + 256 * i;
            int row = c >> 5, off = c & 31;
            size_t gidx = (size_t)t * BH + row * DH + kc * 256 + off * 8;
            *(uint4*)&sAhi[row * AS + off * 8] = *(const uint4*)&g_hs_hi[gidx];
            *(uint4*)&sAlo[row * AS + off * 8] = *(const uint4*)&g_hs_lo[gidx];
        }
        __syncthreads();

#pragma unroll
        for (int kt = 0; kt < 16; kt++) {
            int ktg = kc * 16 + kt;
            uint32 ah0, ah1, ah2, ah3, al0, al1, al2, al3;
            ldsm_x4(ah0, ah1, ah2, ah3, abase_hi + lane_off + (uint32)(kt * 32));
            ldsm_x4(al0, al1, al2, al3, abase_lo + lane_off + (uint32)(kt * 32));
#pragma unroll
            for (int ny = 0; ny < 2; ny++) {
#pragma unroll
                for (int nt = 0; nt < 8; nt++) {
                    int nblk = ny * 16 + nh * 8 + nt;
                    uint4 bf = g_WoF[(nblk * 64 + ktg) * 32 + lane];
                    mma_bf16(C[ny][nt][0], C[ny][nt][1], C[ny][nt][2], C[ny][nt][3],
                             ah0, ah1, ah2, ah3, bf.x, bf.y);
                    mma_bf16(C[ny][nt][0], C[ny][nt][1], C[ny][nt][2], C[ny][nt][3],
                             ah0, ah1, ah2, ah3, bf.z, bf.w);
                    mma_bf16(C[ny][nt][0], C[ny][nt][1], C[ny][nt][2], C[ny][nt][3],
                             al0, al1, al2, al3, bf.x, bf.y);
                }
            }
        }
        __syncthreads();
    }

#pragma unroll
    for (int ny = 0; ny < 2; ny++) {
#pragma unroll
        for (int nt = 0; nt < 8; nt++) {
            int n = ny * 128 + nh * 64 + nt * 8 + 2 * q;
            float2 bv = *(const float2*)&bias[n];
            int m0 = mt * 16 + g;
            float2 v0; v0.x = C[ny][nt][0] + bv.x; v0.y = C[ny][nt][1] + bv.y;
            *(float2*)&out[((size_t)m0 * T_STEPS + t) * DOUT + n] = v0;
            float2 v1; v1.x = C[ny][nt][2] + bv.x; v1.y = C[ny][nt][3] + bv.y;
            *(float2*)&out[((size_t)(m0 + 8) * T_STEPS + t) * DOUT + n] = v1;
        }
    }
}

// ---------------------------------------------------------------------------
extern "C" void kernel_launch(void* const* d_in, const int* in_sizes, int n_in,
                              void* d_out, int out_size) {
    const float* x  = (const float*)d_in[0];  // inputs [B,T,DIN]
    const float* Wi = (const float*)d_in[1];  // input_kernel [DIN,DH]
    const float* Wh = (const float*)d_in[2];  // hidden_kernel [DH,DH]
    const float* bh = (const float*)d_in[3];  // hidden_bias [DH]
    const float* Wo = (const float*)d_in[4];  // output_kernel [DH,DOUT]
    const float* bo = (const float*)d_in[5];  // output_bias [DOUT]
    float* out = (float*)d_out;               // [B,T,DOUT]

    const int scan_smem = 2 * 16 * SA_STRIDE * 2 + 8 * 512 * 4;  // 82432 B
    cudaFuncSetAttribute(k_scan, cudaFuncAttributeMaxDynamicSharedMemorySize,
                         scan_smem);
    const int gemm_smem = 2 * 64 * AS * 2;                       // 67584 B
    cudaFuncSetAttribute(k_xproj_mma, cudaFuncAttributeMaxDynamicSharedMemorySize,
                         gemm_smem);
    cudaFuncSetAttribute(k_out_mma, cudaFuncAttributeMaxDynamicSharedMemorySize,
                         gemm_smem);

    k_prep<<<(128 * 16 * 32 + 32 * 64 * 32) / 256, 256>>>(Wi, Wo);
    k_xproj_mma<<<T_STEPS, 256, gemm_smem>>>(x, bh);
    k_scan<<<SCAN_CTAS, 256, scan_smem>>>(Wh);
    k_out_mma<<<T_STEPS, 256, gemm_smem>>>(bo, out);
}

// round 17
// speedup vs baseline: 1.7144x; 1.7144x over previous
#include <cuda_runtime.h>
#include <cuda_bf16.h>

#define T_STEPS 512
#define BATCH   64
#define DIN     256
#define DH      1024
#define DOUT    256
#define BH      (BATCH * DH)      // 65536
#define SCAN_CTAS 128
#define DOM_ARRIVALS 32           // 32 CTAs per row-group domain
#define SA_STRIDE 1032            // scan: padded bf16 row stride (R11 proven)
#define AS 264                    // GEMM: padded bf16 row stride

typedef unsigned long long ull;
typedef unsigned int uint32;

// Scratch (device globals: allocation-free per harness rules)
__device__ float g_xp[T_STEPS * BH];                 // [T][B][H] input projection
__device__ __nv_bfloat16 g_hs_hi[T_STEPS * BH];      // h high bf16
__device__ __nv_bfloat16 g_hs_lo[T_STEPS * BH];      // h residual bf16
__device__ unsigned int g_barG[T_STEPS * 4 * 32];    // (step, rowgroup) counters
__device__ uint4 g_WiF[128 * 16 * 32];               // W_in  B-frags [nblk][kt][lane]
__device__ uint4 g_WoF[32 * 64 * 32];                // W_out B-frags [nblk][kt][lane]

// ---- bf16 split helpers ---------------------------------------------------
__device__ __forceinline__ void split_bf16(float v, __nv_bfloat16& hi, __nv_bfloat16& lo) {
    hi = __float2bfloat16_rn(v);
    lo = __float2bfloat16_rn(v - __bfloat162float(hi));
}
__device__ __forceinline__ uint32 pack_bf2(__nv_bfloat16 a, __nv_bfloat16 b) {
    __nv_bfloat162 p;
    p.x = a; p.y = b;
    return *(uint32*)&p;
}

// ---- mma / ldmatrix helpers (validated R10/R11) ---------------------------
__device__ __forceinline__ void mma_bf16(float& d0, float& d1, float& d2, float& d3,
                                         uint32 a0, uint32 a1, uint32 a2, uint32 a3,
                                         uint32 b0, uint32 b1) {
    asm volatile(
        "mma.sync.aligned.m16n8k16.row.col.f32.bf16.bf16.f32 "
        "{%0,%1,%2,%3}, {%4,%5,%6,%7}, {%8,%9}, {%0,%1,%2,%3};"
        : "+f"(d0), "+f"(d1), "+f"(d2), "+f"(d3)
        : "r"(a0), "r"(a1), "r"(a2), "r"(a3), "r"(b0), "r"(b1));
}
__device__ __forceinline__ void ldsm_x4(uint32& r0, uint32& r1, uint32& r2, uint32& r3,
                                        uint32 saddr) {
    asm volatile("ldmatrix.sync.aligned.m8n8.x4.shared.b16 {%0,%1,%2,%3}, [%4];"
                 : "=r"(r0), "=r"(r1), "=r"(r2), "=r"(r3) : "r"(saddr));
}

// ---------------------------------------------------------------------------
// Prep: split-bf16 B-fragment arrays for W_in and W_out (validated R11).
// ---------------------------------------------------------------------------
__device__ __forceinline__ uint4 make_frag(const float* __restrict__ W, int ldn,
                                           int n, int k) {
    float w00 = W[k * ldn + n],       w01 = W[(k + 1) * ldn + n];
    float w10 = W[(k + 8) * ldn + n], w11 = W[(k + 9) * ldn + n];
    __nv_bfloat16 h00, l00, h01, l01, h10, l10, h11, l11;
    split_bf16(w00, h00, l00); split_bf16(w01, h01, l01);
    split_bf16(w10, h10, l10); split_bf16(w11, h11, l11);
    uint4 v;
    v.x = pack_bf2(h00, h01);
    v.y = pack_bf2(h10, h11);
    v.z = pack_bf2(l00, l01);
    v.w = pack_bf2(l10, l11);
    return v;
}

__global__ void k_prep(const float* __restrict__ Wi, const float* __restrict__ Wo) {
    int idx = blockIdx.x * 256 + threadIdx.x;
    if (idx < 128 * 16 * 32) {
        int lane = idx & 31;
        int kt   = (idx >> 5) & 15;
        int nblk = idx >> 9;
        g_WiF[idx] = make_frag(Wi, DH, nblk * 8 + (lane >> 2), kt * 16 + 2 * (lane & 3));
    } else {
        int j = idx - 128 * 16 * 32;
        int lane = j & 31;
        int kt   = (j >> 5) & 63;
        int nblk = j >> 11;
        g_WoF[j] = make_frag(Wo, DOUT, nblk * 8 + (lane >> 2), kt * 16 + 2 * (lane & 3));
    }
}

// ---------------------------------------------------------------------------
// Kernel A (tensor): x_proj = x @ W_in + bias. ONE CTA per t, n-loop inside
// (stages x once).
// ---------------------------------------------------------------------------
__global__ void __launch_bounds__(256, 1) k_xproj_mma(const float* __restrict__ x,
                                                      const float* __restrict__ bias) {
    extern __shared__ __align__(16) char smem_raw[];
    __nv_bfloat16* sAhi = (__nv_bfloat16*)smem_raw;   // [64][AS]
    __nv_bfloat16* sAlo = sAhi + 64 * AS;

    const int tid = threadIdx.x, w = tid >> 5, lane = tid & 31;
    const int t = blockIdx.x;
    const int mt = w & 3, nh = w >> 2;
    uint32 abase_hi = (uint32)__cvta_generic_to_shared(sAhi);
    uint32 abase_lo = (uint32)__cvta_generic_to_shared(sAlo);
    const uint32 lane_off = ((uint32)((mt * 16 + (lane & 15)) * AS) +
                            (uint32)((lane >> 4) * 8)) * 2u;
    const int g = lane >> 2, q = lane & 3;

    // stage x[:, t, :] 64x256 fp32 -> split hi/lo bf16 (ONCE)
#pragma unroll
    for (int i = 0; i < 16; i++) {
        int c = tid + 256 * i;
        int row = c >> 6, off = c & 63;
        float4 v = ((const float4*)(x + ((size_t)row * T_STEPS + t) * DIN))[off];
        __nv_bfloat16 h0, l0, h1, l1, h2, l2, h3, l3;
        split_bf16(v.x, h0, l0); split_bf16(v.y, h1, l1);
        split_bf16(v.z, h2, l2); split_bf16(v.w, h3, l3);
        uint2 ph, pl;
        ph.x = pack_bf2(h0, h1); ph.y = pack_bf2(h2, h3);
        pl.x = pack_bf2(l0, l1); pl.y = pack_bf2(l2, l3);
        *(uint2*)&sAhi[row * AS + off * 4] = ph;
        *(uint2*)&sAlo[row * AS + off * 4] = pl;
    }
    __syncthreads();

    for (int nb = 0; nb < 8; nb++) {
        const int n0 = nb * 128;
        float C[8][4] = {};
#pragma unroll
        for (int kt = 0; kt < 16; kt++) {
            uint32 ah0, ah1, ah2, ah3, al0, al1, al2, al3;
            ldsm_x4(ah0, ah1, ah2, ah3, abase_hi + lane_off + (uint32)(kt * 32));
            ldsm_x4(al0, al1, al2, al3, abase_lo + lane_off + (uint32)(kt * 32));
#pragma unroll
            for (int nt = 0; nt < 8; nt++) {
                int nblk = (n0 >> 3) + nh * 8 + nt;
                uint4 bf = g_WiF[(nblk * 16 + kt) * 32 + lane];
                mma_bf16(C[nt][0], C[nt][1], C[nt][2], C[nt][3],
                         ah0, ah1, ah2, ah3, bf.x, bf.y);
                mma_bf16(C[nt][0], C[nt][1], C[nt][2], C[nt][3],
                         ah0, ah1, ah2, ah3, bf.z, bf.w);
                mma_bf16(C[nt][0], C[nt][1], C[nt][2], C[nt][3],
                         al0, al1, al2, al3, bf.x, bf.y);
            }
        }
#pragma unroll
        for (int nt = 0; nt < 8; nt++) {
            int n = n0 + nh * 64 + nt * 8 + 2 * q;
            float2 bv = *(const float2*)&bias[n];
            int m0 = mt * 16 + g;
            float2 v0; v0.x = C[nt][0] + bv.x; v0.y = C[nt][1] + bv.y;
            *(float2*)&g_xp[(size_t)t * BH + m0 * DH + n] = v0;
            float2 v1; v1.x = C[nt][2] + bv.x; v1.y = C[nt][3] + bv.y;
            *(float2*)&g_xp[(size_t)t * BH + (m0 + 8) * DH + n] = v1;
        }
    }
}

// ---------------------------------------------------------------------------
// Barrier (R9/R11, proven)
// ---------------------------------------------------------------------------
__device__ __forceinline__ unsigned int* rg_ctr(int rb, int t) {
    return &g_barG[(t * 4 + rb) * 32];
}

__device__ __forceinline__ void rg_barrier(int t, int rb, bool resetter) {
    __syncthreads();
    if (threadIdx.x == 0) {
        unsigned int* ctr = rg_ctr(rb, t);
        asm volatile("red.release.gpu.global.add.u32 [%0], 1;"
                     :: "l"(ctr) : "memory");
        unsigned int v;
        do {
            asm volatile("ld.relaxed.gpu.global.u32 %0, [%1];"
                         : "=r"(v) : "l"(ctr) : "memory");
        } while (v < DOM_ARRIVALS);
        asm volatile("ld.acquire.gpu.global.u32 %0, [%1];"
                     : "=r"(v) : "l"(ctr) : "memory");
        if (resetter && t > 0) {
            asm volatile("st.relaxed.gpu.global.u32 [%0], 0;"
                         :: "l"(rg_ctr(rb, t - 1)) : "memory");
        }
    }
    __syncthreads();
}

// ---------------------------------------------------------------------------
// Kernel B: persistent tensor-core scan — EXACT R11 body (proven 3.2us/step):
// CTA-wide coalesced staging into [16][SA_STRIDE] hi/lo, ldmatrix, 3-product
// split-bf16 MMA, SMEM K-reduction, row-group barrier.
// ---------------------------------------------------------------------------
__global__ void __launch_bounds__(256, 1) k_scan(const float* __restrict__ Wh) {
    extern __shared__ __align__(16) char smem_raw[];
    __nv_bfloat16* sA_hi = (__nv_bfloat16*)smem_raw;                  // [16][SA_STRIDE]
    __nv_bfloat16* sA_lo = sA_hi + 16 * SA_STRIDE;                    // [16][SA_STRIDE]
    float*         sRed  = (float*)(sA_lo + 16 * SA_STRIDE);          // [8][512]

    const int tid  = threadIdx.x;
    const int w    = tid >> 5;
    const int lane = tid & 31;
    const int rb   = blockIdx.x >> 5;
    const int cb   = blockIdx.x & 31;
    const int row0 = rb * 16;
    const bool resetter = (cb == 0);

    if (resetter && tid == 0) {
        *rg_ctr(rb, T_STEPS - 2) = 0;
    }

    uint32 Bhi[4][8][2], Blo[4][8][2];
    {
        const int nn = cb * 32 + (lane >> 2);
#pragma unroll
        for (int nt = 0; nt < 4; nt++) {
            const int n = nn + nt * 8;
#pragma unroll
            for (int kt = 0; kt < 8; kt++) {
                const int kbase = w * 128 + kt * 16 + 2 * (lane & 3);
#pragma unroll
                for (int half = 0; half < 2; half++) {
                    const int k = kbase + half * 8;
                    float w0 = Wh[k * DH + n];
                    float w1 = Wh[(k + 1) * DH + n];
                    __nv_bfloat16 h0, l0, h1, l1;
                    split_bf16(w0, h0, l0);
                    split_bf16(w1, h1, l1);
                    Bhi[nt][kt][half] = pack_bf2(h0, h1);
                    Blo[nt][kt][half] = pack_bf2(l0, l1);
                }
            }
        }
    }

    const int erow = tid >> 4;
    const int ecol = (tid & 15) * 2;
    const int grow = row0 + erow;
    const int gcol = cb * 32 + ecol;

    {
        float2 xv = *(const float2*)&g_xp[grow * DH + gcol];
        float v0 = tanhf(xv.x), v1 = tanhf(xv.y);
        __nv_bfloat16 h0, l0, h1, l1;
        split_bf16(v0, h0, l0);
        split_bf16(v1, h1, l1);
        *(uint32*)&g_hs_hi[grow * DH + gcol] = pack_bf2(h0, h1);
        *(uint32*)&g_hs_lo[grow * DH + gcol] = pack_bf2(l0, l1);
    }
    rg_barrier(0, rb, resetter);

    uint32 sa_hi_base = (uint32)__cvta_generic_to_shared(sA_hi);
    uint32 sa_lo_base = (uint32)__cvta_generic_to_shared(sA_lo);
    const uint32 lane_off = ((uint32)(lane & 15) * SA_STRIDE + (uint32)(w * 128) +
                            (uint32)((lane >> 4) * 8)) * 2u;

    for (int t = 1; t < T_STEPS; t++) {
        float2 xv = *(const float2*)&g_xp[t * BH + grow * DH + gcol];

        {
            const uint4* srcH = (const uint4*)(g_hs_hi + (size_t)(t - 1) * BH + row0 * DH);
            const uint4* srcL = (const uint4*)(g_hs_lo + (size_t)(t - 1) * BH + row0 * DH);
#pragma unroll
            for (int i = 0; i < 8; i++) {
                int c   = tid + 256 * i;
                int row = c >> 7;
                int off = c & 127;
                *(uint4*)(sA_hi + row * SA_STRIDE + off * 8) = srcH[c];
                *(uint4*)(sA_lo + row * SA_STRIDE + off * 8) = srcL[c];
            }
        }
        __syncthreads();

        float C[4][4];
#pragma unroll
        for (int nt = 0; nt < 4; nt++)
#pragma unroll
            for (int i = 0; i < 4; i++) C[nt][i] = 0.f;

#pragma unroll
        for (int kt = 0; kt < 8; kt++) {
            uint32 ah0, ah1, ah2, ah3, al0, al1, al2, al3;
            ldsm_x4(ah0, ah1, ah2, ah3, sa_hi_base + lane_off + (uint32)(kt * 32));
            ldsm_x4(al0, al1, al2, al3, sa_lo_base + lane_off + (uint32)(kt * 32));
#pragma unroll
            for (int nt = 0; nt < 4; nt++) {
                mma_bf16(C[nt][0], C[nt][1], C[nt][2], C[nt][3],
                         ah0, ah1, ah2, ah3, Bhi[nt][kt][0], Bhi[nt][kt][1]);
                mma_bf16(C[nt][0], C[nt][1], C[nt][2], C[nt][3],
                         ah0, ah1, ah2, ah3, Blo[nt][kt][0], Blo[nt][kt][1]);
                mma_bf16(C[nt][0], C[nt][1], C[nt][2], C[nt][3],
                         al0, al1, al2, al3, Bhi[nt][kt][0], Bhi[nt][kt][1]);
            }
        }

        {
            const int g = lane >> 2;
            const int q = lane & 3;
            float* base = sRed + w * 512;
#pragma unroll
            for (int nt = 0; nt < 4; nt++) {
                const int coln = nt * 8 + 2 * q;
                float2 lo2; lo2.x = C[nt][0]; lo2.y = C[nt][1];
                float2 hi2; hi2.x = C[nt][2]; hi2.y = C[nt][3];
                *(float2*)&base[g * 32 + coln]        = lo2;
                *(float2*)&base[(g + 8) * 32 + coln]  = hi2;
            }
        }
        __syncthreads();

        {
            const int o = erow * 32 + ecol;
            float2 s = {0.f, 0.f};
#pragma unroll
            for (int ww = 0; ww < 8; ww++) {
                float2 v = *(const float2*)&sRed[ww * 512 + o];
                s.x += v.x;
                s.y += v.y;
            }
            float v0 = tanhf(xv.x + s.x);
            float v1 = tanhf(xv.y + s.y);
            __nv_bfloat16 h0, l0, h1, l1;
            split_bf16(v0, h0, l0);
            split_bf16(v1, h1, l1);
            *(uint32*)&g_hs_hi[(size_t)t * BH + grow * DH + gcol] = pack_bf2(h0, h1);
            *(uint32*)&g_hs_lo[(size_t)t * BH + grow * DH + gcol] = pack_bf2(l0, l1);
        }

        if (t != T_STEPS - 1)
            rg_barrier(t, rb, resetter);
    }
}

// ---------------------------------------------------------------------------
// Kernel C (tensor): out = hs @ W_out + bias. ONE CTA per t; kc outer,
// both n-halves inner (151us at normal clocks, best same-round reading).
// ---------------------------------------------------------------------------
__global__ void __launch_bounds__(256, 1) k_out_mma(const float* __restrict__ bias,
                                                    float* __restrict__ out) {
    extern __shared__ __align__(16) char smem_raw[];
    __nv_bfloat16* sAhi = (__nv_bfloat16*)smem_raw;   // [64][AS]
    __nv_bfloat16* sAlo = sAhi + 64 * AS;

    const int tid = threadIdx.x, w = tid >> 5, lane = tid & 31;
    const int t = blockIdx.x;
    const int mt = w & 3, nh = w >> 2;
    uint32 abase_hi = (uint32)__cvta_generic_to_shared(sAhi);
    uint32 abase_lo = (uint32)__cvta_generic_to_shared(sAlo);
    const uint32 lane_off = ((uint32)((mt * 16 + (lane & 15)) * AS) +
                            (uint32)((lane >> 4) * 8)) * 2u;
    const int g = lane >> 2, q = lane & 3;

    float C[2][8][4] = {};

    for (int kc = 0; kc < 4; kc++) {
#pragma unroll
        for (int i = 0; i < 8; i++) {
            int c = tid + 256 * i;
            int row = c >> 5, off = c & 31;
            size_t gidx = (size_t)t * BH + row * DH + kc * 256 + off * 8;
            *(uint4*)&sAhi[row * AS + off * 8] = *(const uint4*)&g_hs_hi[gidx];
            *(uint4*)&sAlo[row * AS + off * 8] = *(const uint4*)&g_hs_lo[gidx];
        }
        __syncthreads();

#pragma unroll
        for (int kt = 0; kt < 16; kt++) {
            int ktg = kc * 16 + kt;
            uint32 ah0, ah1, ah2, ah3, al0, al1, al2, al3;
            ldsm_x4(ah0, ah1, ah2, ah3, abase_hi + lane_off + (uint32)(kt * 32));
            ldsm_x4(al0, al1, al2, al3, abase_lo + lane_off + (uint32)(kt * 32));
#pragma unroll
            for (int ny = 0; ny < 2; ny++) {
#pragma unroll
                for (int nt = 0; nt < 8; nt++) {
                    int nblk = ny * 16 + nh * 8 + nt;
                    uint4 bf = g_WoF[(nblk * 64 + ktg) * 32 + lane];
                    mma_bf16(C[ny][nt][0], C[ny][nt][1], C[ny][nt][2], C[ny][nt][3],
                             ah0, ah1, ah2, ah3, bf.x, bf.y);
                    mma_bf16(C[ny][nt][0], C[ny][nt][1], C[ny][nt][2], C[ny][nt][3],
                             ah0, ah1, ah2, ah3, bf.z, bf.w);
                    mma_bf16(C[ny][nt][0], C[ny][nt][1], C[ny][nt][2], C[ny][nt][3],
                             al0, al1, al2, al3, bf.x, bf.y);
                }
            }
        }
        __syncthreads();
    }

#pragma unroll
    for (int ny = 0; ny < 2; ny++) {
#pragma unroll
        for (int nt = 0; nt < 8; nt++) {
            int n = ny * 128 + nh * 64 + nt * 8 + 2 * q;
            float2 bv = *(const float2*)&bias[n];
            int m0 = mt * 16 + g;
            float2 v0; v0.x = C[ny][nt][0] + bv.x; v0.y = C[ny][nt][1] + bv.y;
            *(float2*)&out[((size_t)m0 * T_STEPS + t) * DOUT + n] = v0;
            float2 v1; v1.x = C[ny][nt][2] + bv.x; v1.y = C[ny][nt][3] + bv.y;
            *(float2*)&out[((size_t)(m0 + 8) * T_STEPS + t) * DOUT + n] = v1;
        }
    }
}

// ---------------------------------------------------------------------------
extern "C" void kernel_launch(void* const* d_in, const int* in_sizes, int n_in,
                              void* d_out, int out_size) {
    const float* x  = (const float*)d_in[0];  // inputs [B,T,DIN]
    const float* Wi = (const float*)d_in[1];  // input_kernel [DIN,DH]
    const float* Wh = (const float*)d_in[2];  // hidden_kernel [DH,DH]
    const float* bh = (const float*)d_in[3];  // hidden_bias [DH]
    const float* Wo = (const float*)d_in[4];  // output_kernel [DH,DOUT]
    const float* bo = (const float*)d_in[5];  // output_bias [DOUT]
    float* out = (float*)d_out;               // [B,T,DOUT]

    const int scan_smem = 2 * 16 * SA_STRIDE * 2 + 8 * 512 * 4;  // 82432 B
    cudaFuncSetAttribute(k_scan, cudaFuncAttributeMaxDynamicSharedMemorySize,
                         scan_smem);
    const int gemm_smem = 2 * 64 * AS * 2;                       // 67584 B
    cudaFuncSetAttribute(k_xproj_mma, cudaFuncAttributeMaxDynamicSharedMemorySize,
                         gemm_smem);
    cudaFuncSetAttribute(k_out_mma, cudaFuncAttributeMaxDynamicSharedMemorySize,
                         gemm_smem);

    k_prep<<<(128 * 16 * 32 + 32 * 64 * 32) / 256, 256>>>(Wi, Wo);
    k_xproj_mma<<<T_STEPS, 256, gemm_smem>>>(x, bh);
    k_scan<<<SCAN_CTAS, 256, scan_smem>>>(Wh);
    k_out_mma<<<T_STEPS, 256, gemm_smem>>>(bo, out);
}